// round 1
// baseline (speedup 1.0000x reference)
#include <cuda_runtime.h>
#include <math.h>

#define NN 100000
#define NE 3200000
#define INF_ 128
#define F1 32
#define F2 16

// ---------------- scratch (static device globals; no allocation) ----------------
__device__ float g_dinv[NN];          // deg accumulator -> rsqrt(deg+1)
__device__ int   g_cnt[NN];           // in-degree counts
__device__ int   g_row[NN + 1];       // CSR row offsets
__device__ int   g_cur[NN];           // scatter cursors
__device__ int2  g_cedge[NE];         // (src, norm-as-int) packed per CSR slot
__device__ float g_h1[NN * F1];       // x @ W1
__device__ float g_hrelu[NN * F1];    // relu(layer1 out)
__device__ float g_h2[NN * F2];       // hrelu @ W2

// ---------------- kernels ----------------

__global__ void k_zero() {
    int i = blockIdx.x * blockDim.x + threadIdx.x;
    if (i < NN) { g_dinv[i] = 0.0f; g_cnt[i] = 0; }
}

// per edge: accumulate weighted in-degree and integer count at dst
__global__ void k_count_deg(const int* __restrict__ ei, const float* __restrict__ ew) {
    int e = blockIdx.x * blockDim.x + threadIdx.x;
    if (e >= NE) return;
    int d = ei[NE + e];
    atomicAdd(&g_dinv[d], ew[e]);
    atomicAdd(&g_cnt[d], 1);
}

__global__ void k_dinv() {
    int i = blockIdx.x * blockDim.x + threadIdx.x;
    if (i < NN) g_dinv[i] = rsqrtf(g_dinv[i] + 1.0f);
}

// single-block 2-level scan of g_cnt -> g_row (exclusive), g_cur copy
#define SCAN_T 1024
#define SCAN_C 98   // ceil(100000/1024)
__global__ void k_scan() {
    __shared__ int sh[SCAN_T];
    int t = threadIdx.x;
    int base = t * SCAN_C;
    int end = min(base + SCAN_C, NN);
    int s = 0;
    for (int i = base; i < end; i++) s += g_cnt[i];
    sh[t] = s;
    __syncthreads();
    // Hillis-Steele inclusive scan
    for (int off = 1; off < SCAN_T; off <<= 1) {
        int v = (t >= off) ? sh[t - off] : 0;
        __syncthreads();
        sh[t] += v;
        __syncthreads();
    }
    int run = (t == 0) ? 0 : sh[t - 1];
    for (int i = base; i < end; i++) {
        g_row[i] = run;
        g_cur[i] = run;
        run += g_cnt[i];
    }
    if (t == SCAN_T - 1) g_row[NN] = sh[SCAN_T - 1];
}

// per edge: compute norm, scatter (src, norm) into CSR slot of dst
__global__ void k_scatter(const int* __restrict__ ei, const float* __restrict__ ew) {
    int e = blockIdx.x * blockDim.x + threadIdx.x;
    if (e >= NE) return;
    int s = ei[e];
    int d = ei[NE + e];
    float nrm = g_dinv[s] * ew[e] * g_dinv[d];
    int pos = atomicAdd(&g_cur[d], 1);
    g_cedge[pos] = make_int2(s, __float_as_int(nrm));
}

// h1 = x @ W1   [N,128]x[128,32], thread-per-node, W1 in smem
__global__ void k_gemm1(const float* __restrict__ x, const float* __restrict__ W1) {
    __shared__ float sW[INF_ * F1];   // 16 KB
    int tid = threadIdx.x;
    for (int i = tid; i < INF_ * F1; i += blockDim.x) sW[i] = W1[i];
    __syncthreads();
    int n = blockIdx.x * blockDim.x + tid;
    if (n >= NN) return;
    float acc[F1];
#pragma unroll
    for (int j = 0; j < F1; j++) acc[j] = 0.0f;
    const float4* xr = (const float4*)(x + (size_t)n * INF_);
    const float4* sW4 = (const float4*)sW;
    for (int k4 = 0; k4 < INF_ / 4; k4++) {
        float4 xv = xr[k4];
        float xs[4] = {xv.x, xv.y, xv.z, xv.w};
#pragma unroll
        for (int kk = 0; kk < 4; kk++) {
            const float4* wrow = sW4 + (k4 * 4 + kk) * (F1 / 4);
#pragma unroll
            for (int j4 = 0; j4 < F1 / 4; j4++) {
                float4 w = wrow[j4];
                acc[j4 * 4 + 0] += xs[kk] * w.x;
                acc[j4 * 4 + 1] += xs[kk] * w.y;
                acc[j4 * 4 + 2] += xs[kk] * w.z;
                acc[j4 * 4 + 3] += xs[kk] * w.w;
            }
        }
    }
    float* o = g_h1 + (size_t)n * F1;
#pragma unroll
    for (int j = 0; j < F1; j++) o[j] = acc[j];
}

// layer1 aggregation + finalize: warp-per-node, lane = feature (32)
__global__ void k_agg1(const float* __restrict__ b1) {
    int lane = threadIdx.x & 31;
    int n = blockIdx.x * (blockDim.x >> 5) + (threadIdx.x >> 5);
    if (n >= NN) return;
    int beg = g_row[n], end = g_row[n + 1];
    float acc = 0.0f;
    int i = beg;
    for (; i + 1 < end; i += 2) {
        int2 a = g_cedge[i];
        int2 b = g_cedge[i + 1];
        acc += __int_as_float(a.y) * g_h1[(size_t)a.x * F1 + lane];
        acc += __int_as_float(b.y) * g_h1[(size_t)b.x * F1 + lane];
    }
    if (i < end) {
        int2 a = g_cedge[i];
        acc += __int_as_float(a.y) * g_h1[(size_t)a.x * F1 + lane];
    }
    float di = g_dinv[n];
    float x1 = acc + g_h1[(size_t)n * F1 + lane] * di * di + b1[lane];
    g_hrelu[(size_t)n * F1 + lane] = fmaxf(x1, 0.0f);
}

// h2 = hrelu @ W2  [N,32]x[32,16], thread-per-node, W2 in smem
__global__ void k_gemm2(const float* __restrict__ W2) {
    __shared__ float sW[F1 * F2];   // 2 KB
    int tid = threadIdx.x;
    for (int i = tid; i < F1 * F2; i += blockDim.x) sW[i] = W2[i];
    __syncthreads();
    int n = blockIdx.x * blockDim.x + tid;
    if (n >= NN) return;
    float acc[F2];
#pragma unroll
    for (int j = 0; j < F2; j++) acc[j] = 0.0f;
    const float4* hr = (const float4*)(g_hrelu + (size_t)n * F1);
    const float4* sW4 = (const float4*)sW;
    for (int k4 = 0; k4 < F1 / 4; k4++) {
        float4 hv = hr[k4];
        float hs[4] = {hv.x, hv.y, hv.z, hv.w};
#pragma unroll
        for (int kk = 0; kk < 4; kk++) {
            const float4* wrow = sW4 + (k4 * 4 + kk) * (F2 / 4);
#pragma unroll
            for (int j4 = 0; j4 < F2 / 4; j4++) {
                float4 w = wrow[j4];
                acc[j4 * 4 + 0] += hs[kk] * w.x;
                acc[j4 * 4 + 1] += hs[kk] * w.y;
                acc[j4 * 4 + 2] += hs[kk] * w.z;
                acc[j4 * 4 + 3] += hs[kk] * w.w;
            }
        }
    }
    float* o = g_h2 + (size_t)n * F2;
#pragma unroll
    for (int j = 0; j < F2; j++) o[j] = acc[j];
}

// layer2 aggregation + full FC head; warp-per-node.
// lanes split: f = lane&15 (feature), half = lane>>4 (edge interleave x2)
__global__ void k_agg2_final(const float* __restrict__ b2,
                             const float* __restrict__ fc1_w, const float* __restrict__ fc1_b,
                             const float* __restrict__ fc2_w, const float* __restrict__ fc2_b,
                             float* __restrict__ out) {
    int lane = threadIdx.x & 31;
    int n = blockIdx.x * (blockDim.x >> 5) + (threadIdx.x >> 5);
    if (n >= NN) return;
    int f = lane & 15;
    int half = lane >> 4;
    int beg = g_row[n], end = g_row[n + 1];
    float acc = 0.0f;
    for (int i = beg + half; i < end; i += 2) {
        int2 a = g_cedge[i];
        acc += __int_as_float(a.y) * g_h2[(size_t)a.x * F2 + f];
    }
    // fold the two edge-halves: lane L (<16) += lane L+16
    acc += __shfl_down_sync(0xffffffffu, acc, 16);
    float di = g_dinv[n];
    float x2 = acc + g_h2[(size_t)n * F2 + f] * di * di + b2[f];   // valid on lanes 0..15
    // x1f = dot(x2, fc1_w) + fc1_b  (reduce over 16 lanes)
    float p = x2 * fc1_w[f];
#pragma unroll
    for (int off = 8; off >= 1; off >>= 1) p += __shfl_xor_sync(0xffffffffu, p, off);
    float x1f = p + fc1_b[0];
    float c = 1.0f / (1.0f + expf(-x1f));
    // r = dot(hrelu[n,0:32], fc2_w[0:32]) + c*fc2_w[32] + fc2_b
    float q = g_hrelu[(size_t)n * F1 + f] * fc2_w[f]
            + g_hrelu[(size_t)n * F1 + 16 + f] * fc2_w[16 + f];
#pragma unroll
    for (int off = 8; off >= 1; off >>= 1) q += __shfl_xor_sync(0xffffffffu, q, off);
    float r = q + c * fc2_w[32] + fc2_b[0];
    if (lane == 0) {
        out[n] = r;
        out[NN + n] = x1f;
    }
}

// ---------------- launch ----------------
extern "C" void kernel_launch(void* const* d_in, const int* in_sizes, int n_in,
                              void* d_out, int out_size) {
    const float* x     = (const float*)d_in[0];
    const int*   ei    = (const int*)  d_in[1];
    const float* ew    = (const float*)d_in[2];
    const float* W1    = (const float*)d_in[3];
    const float* b1    = (const float*)d_in[4];
    const float* W2    = (const float*)d_in[5];
    const float* b2    = (const float*)d_in[6];
    const float* fc1w  = (const float*)d_in[7];
    const float* fc1b  = (const float*)d_in[8];
    const float* fc2w  = (const float*)d_in[9];
    const float* fc2b  = (const float*)d_in[10];
    float* out = (float*)d_out;

    const int TB = 256;
    const int gN = (NN + TB - 1) / TB;       // 391
    const int gE = (NE + TB - 1) / TB;       // 12500
    const int gW = (NN * 32 + TB - 1) / TB;  // warp-per-node grids: 8 nodes/block -> 12500
    (void)in_sizes; (void)n_in; (void)out_size;

    k_zero<<<gN, TB>>>();
    k_count_deg<<<gE, TB>>>(ei, ew);
    k_gemm1<<<gN, TB>>>(x, W1);              // independent of degree path
    k_dinv<<<gN, TB>>>();
    k_scan<<<1, SCAN_T>>>();
    k_scatter<<<gE, TB>>>(ei, ew);
    k_agg1<<<gW, TB>>>(b1);
    k_gemm2<<<gN, TB>>>(W2);
    k_agg2_final<<<gW, TB>>>(b2, fc1w, fc1b, fc2w, fc2b, out);
}